// round 9
// baseline (speedup 1.0000x reference)
#include <cuda_runtime.h>
#include <cuda_bf16.h>
#include <cuda_fp16.h>
#include <math.h>
#include <stdint.h>

#define B_   8
#define N_   4096
#define C_   768
#define H_   12
#define D_   64
#define C3_  2304
#define BH_  (B_*H_)
#define NSPLIT 8
#define TOK_PER_SPLIT (N_/NSPLIT)   // 512
#define QCH  32                      // tokens per qk chunk
#define NCHUNK (TOK_PER_SPLIT/QCH)   // 16

// ---- scratch (device globals; no runtime allocation allowed) ----
__device__ float g_attn_part[NSPLIT][BH_][D_][D_];
__device__ float g_qnorm_part[NSPLIT][BH_][D_];
__device__ __half g_M[B_][C_][C_];                 // fused attn*W (fp16)
__device__ __half g_V[(size_t)B_*N_*C_];           // v slice of x (fp16)

// ============================================================
// helpers
// ============================================================
__device__ __forceinline__ void mma16816(float c[4],
                                         const uint32_t a[4],
                                         uint32_t b0, uint32_t b1) {
    asm volatile(
        "mma.sync.aligned.m16n8k16.row.col.f32.f16.f16.f32 "
        "{%0,%1,%2,%3}, {%4,%5,%6,%7}, {%8,%9}, {%0,%1,%2,%3};"
        : "+f"(c[0]), "+f"(c[1]), "+f"(c[2]), "+f"(c[3])
        : "r"(a[0]), "r"(a[1]), "r"(a[2]), "r"(a[3]), "r"(b0), "r"(b1));
}

__device__ __forceinline__ uint32_t smem_u32(const void* p) {
    uint32_t a;
    asm("{ .reg .u64 t; cvta.to.shared.u64 t, %1; cvt.u32.u64 %0, t; }" : "=r"(a) : "l"(p));
    return a;
}

#define LDSM4(r, addr) \
    asm volatile("ldmatrix.sync.aligned.m8n8.x4.shared.b16 {%0,%1,%2,%3}, [%4];" \
        : "=r"((r)[0]), "=r"((r)[1]), "=r"((r)[2]), "=r"((r)[3]) : "r"(addr))

#define CP16(dst, src) \
    asm volatile("cp.async.cg.shared.global [%0], [%1], 16;" :: "r"(dst), "l"(src))
#define CPCOMMIT() asm volatile("cp.async.commit_group;" ::: "memory")
#define CPWAIT2()  asm volatile("cp.async.wait_group 2;" ::: "memory")

// ============================================================
// Kernel 1: per (b,h,split): attn_part = q @ khat^T (+ Sum q^2 partials)
//   32-token chunks, double-buffered smem, register prefetch.
//   Loads: 8 threads per token, 8 floats each.
// ============================================================
__global__ void __launch_bounds__(256) qk_kernel(const float* __restrict__ x) {
    const int bh    = blockIdx.x;
    const int b     = bh / H_;
    const int h     = bh % H_;
    const int split = blockIdx.y;
    const int t     = threadIdx.x;

    const int tok = t >> 3;      // token in chunk (0..31)
    const int gi  = t & 7;       // 8-float group within 64 (0..7)
    const int ti  = t & 15;      // output i-quad
    const int tj  = t >> 4;      // output j-quad

    __shared__ float qs[2][QCH][68];
    __shared__ float ks[2][QCH][68];
    __shared__ float qn[64];
    if (t < 64) qn[t] = 0.f;

    float qsq[8];
    #pragma unroll
    for (int i = 0; i < 8; i++) qsq[i] = 0.f;
    float acc[4][4];
    #pragma unroll
    for (int a = 0; a < 4; a++)
        #pragma unroll
        for (int c = 0; c < 4; c++) acc[a][c] = 0.f;

    const float* xb = x + (size_t)b * N_ * C3_ + h * D_ + gi * 8;
    const int nbeg = split * TOK_PER_SPLIT;

    float4 qa, qb, ka, kb;

    #define QK_LOAD(n0) do {                                             \
        const float* row = xb + (size_t)((n0) + tok) * C3_;              \
        qa = *(const float4*)(row);                                      \
        qb = *(const float4*)(row + 4);                                  \
        ka = *(const float4*)(row + C_);                                 \
        kb = *(const float4*)(row + C_ + 4);                             \
    } while (0)

    #define QK_PREP(buf) do {                                            \
        float s = ka.x*ka.x + ka.y*ka.y + ka.z*ka.z + ka.w*ka.w          \
                + kb.x*kb.x + kb.y*kb.y + kb.z*kb.z + kb.w*kb.w;         \
        s += __shfl_xor_sync(0xffffffffu, s, 1);                         \
        s += __shfl_xor_sync(0xffffffffu, s, 2);                         \
        s += __shfl_xor_sync(0xffffffffu, s, 4);                         \
        float inv = 1.0f / fmaxf(sqrtf(s), 1e-12f);                      \
        ka.x *= inv; ka.y *= inv; ka.z *= inv; ka.w *= inv;              \
        kb.x *= inv; kb.y *= inv; kb.z *= inv; kb.w *= inv;              \
        qsq[0] += qa.x*qa.x; qsq[1] += qa.y*qa.y;                        \
        qsq[2] += qa.z*qa.z; qsq[3] += qa.w*qa.w;                        \
        qsq[4] += qb.x*qb.x; qsq[5] += qb.y*qb.y;                        \
        qsq[6] += qb.z*qb.z; qsq[7] += qb.w*qb.w;                        \
        *(float4*)&qs[buf][tok][gi * 8]     = qa;                        \
        *(float4*)&qs[buf][tok][gi * 8 + 4] = qb;                        \
        *(float4*)&ks[buf][tok][gi * 8]     = ka;                        \
        *(float4*)&ks[buf][tok][gi * 8 + 4] = kb;                        \
    } while (0)

    QK_LOAD(nbeg);
    QK_PREP(0);
    __syncthreads();

    for (int c = 0; c < NCHUNK; c++) {
        if (c + 1 < NCHUNK) QK_LOAD(nbeg + (c + 1) * QCH);

        const float (*q)[68] = qs[c & 1];
        const float (*k)[68] = ks[c & 1];
        #pragma unroll
        for (int nn = 0; nn < QCH; nn++) {
            float4 aq = *(const float4*)&q[nn][ti * 4];
            float4 bk = *(const float4*)&k[nn][tj * 4];
            float aa[4] = {aq.x, aq.y, aq.z, aq.w};
            float bb[4] = {bk.x, bk.y, bk.z, bk.w};
            #pragma unroll
            for (int ii = 0; ii < 4; ii++)
                #pragma unroll
                for (int jj = 0; jj < 4; jj++)
                    acc[ii][jj] = fmaf(aa[ii], bb[jj], acc[ii][jj]);
        }

        if (c + 1 < NCHUNK) QK_PREP((c + 1) & 1);
        __syncthreads();
    }

    #pragma unroll
    for (int ii = 0; ii < 4; ii++)
        #pragma unroll
        for (int jj = 0; jj < 4; jj++)
            g_attn_part[split][bh][ti * 4 + ii][tj * 4 + jj] = acc[ii][jj];

    // q^2 partial reduce: lanes with same gi (xor 8, 16), then atomics
    #pragma unroll
    for (int i = 0; i < 8; i++) {
        qsq[i] += __shfl_xor_sync(0xffffffffu, qsq[i], 8);
        qsq[i] += __shfl_xor_sync(0xffffffffu, qsq[i], 16);
    }
    if (((t >> 3) & 3) == 0) {
        #pragma unroll
        for (int i = 0; i < 8; i++)
            atomicAdd(&qn[gi * 8 + i], qsq[i]);
    }
    __syncthreads();
    if (t < 64) g_qnorm_part[split][bh][t] = qn[t];
}

// ============================================================
// Kernel 2: convert V slice of x to fp16 (A operand)
// ============================================================
__global__ void __launch_bounds__(256) xvcvt_kernel(const float* __restrict__ x) {
    const size_t f = ((size_t)blockIdx.x * 256 + threadIdx.x) * 8;   // flat [B*N*C]
    const size_t bn = f / C_;
    const int   c  = (int)(f % C_);
    const float* p = x + bn * C3_ + 2 * C_ + c;
    float4 v0 = *(const float4*)(p);
    float4 v1 = *(const float4*)(p + 4);
    __half2 h0 = __floats2half2_rn(v0.x, v0.y);
    __half2 h1 = __floats2half2_rn(v0.z, v0.w);
    __half2 h2 = __floats2half2_rn(v1.x, v1.y);
    __half2 h3 = __floats2half2_rn(v1.z, v1.w);
    uint4 o;
    o.x = *(uint32_t*)&h0; o.y = *(uint32_t*)&h1;
    o.z = *(uint32_t*)&h2; o.w = *(uint32_t*)&h3;
    *(uint4*)&g_V[f] = o;
}

// ============================================================
// Kernel 3 (fused softmax + weight fold):
//   softmax rows in-smem, then M[b][c'][h*64+j] = sum_i W[c'][h*64+i]*attn[i][j]
// ============================================================
__global__ void __launch_bounds__(256) mproj_kernel(const float* __restrict__ w,
                                                    const float* __restrict__ temp) {
    const int bh = blockIdx.x;
    const int b  = bh / H_;
    const int hh = bh % H_;
    const int t  = threadIdx.x;

    __shared__ float as[64][64];

    if (t < 64) {
        const int i = t;
        float qn2 = 0.f;
        #pragma unroll
        for (int s = 0; s < NSPLIT; s++) qn2 += g_qnorm_part[s][bh][i];
        const float invq   = 1.0f / fmaxf(sqrtf(qn2), 1e-12f);
        const float tscale = temp[hh] * invq;

        float v[64];
        float mx = -1e30f;
        #pragma unroll
        for (int j = 0; j < 64; j++) {
            float a = 0.f;
            #pragma unroll
            for (int s = 0; s < NSPLIT; s++) a += g_attn_part[s][bh][i][j];
            a *= tscale;
            v[j] = a;
            mx = fmaxf(mx, a);
        }
        float sum = 0.f;
        #pragma unroll
        for (int j = 0; j < 64; j++) { v[j] = expf(v[j] - mx); sum += v[j]; }
        const float r = 1.0f / sum;
        #pragma unroll
        for (int j = 0; j < 64; j++) as[i][j] = v[j] * r;
    }
    __syncthreads();

    for (int rr = 0; rr < 3; rr++) {
        const int cp = t + rr * 256;
        const float4* wrow = (const float4*)(w + (size_t)cp * C_ + hh * D_);
        float m[64];
        #pragma unroll
        for (int j = 0; j < 64; j++) m[j] = 0.f;

        for (int i4 = 0; i4 < 16; i4++) {
            float4 w4 = wrow[i4];
            float wv[4] = {w4.x, w4.y, w4.z, w4.w};
            #pragma unroll
            for (int s = 0; s < 4; s++) {
                const int i = i4 * 4 + s;
                #pragma unroll
                for (int jv = 0; jv < 16; jv++) {
                    float4 a4 = *(const float4*)&as[i][jv * 4];
                    m[jv*4+0] = fmaf(wv[s], a4.x, m[jv*4+0]);
                    m[jv*4+1] = fmaf(wv[s], a4.y, m[jv*4+1]);
                    m[jv*4+2] = fmaf(wv[s], a4.z, m[jv*4+2]);
                    m[jv*4+3] = fmaf(wv[s], a4.w, m[jv*4+3]);
                }
            }
        }
        #pragma unroll
        for (int p = 0; p < 32; p++) {
            __half2 hv = __floats2half2_rn(m[2*p], m[2*p+1]);
            *(uint32_t*)&g_M[b][cp][hh*64 + 2*p] = *(uint32_t*)&hv;
        }
    }
}

// ============================================================
// Kernel 4: out[b,m,c'] = sum_k V[b,m,k]*M[b][c'][k] + bias (fp16 HMMA)
//   CTA 128x128, 16 warps (4x4), warp tile 32x32, k-step 32,
//   4-stage cp.async, ldmatrix.x4.
// ============================================================
#define KPITCH 40            // fp16 units per smem row (80B, conflict-free)
#define AREG_B 0             // region byte offsets within a stage
#define BREG_B 10240
#define ST_B   20480         // stage size in bytes
#define NSTAGE 4
#define GSMEM  (NSTAGE * ST_B)

__global__ void __launch_bounds__(512, 1)
gemm_kernel(const float* __restrict__ bias, float* __restrict__ out) {
    extern __shared__ __half sm[];
    const uint32_t sbase = smem_u32(sm);
    const int t    = threadIdx.x;
    const int lane = t & 31;
    const int warp = t >> 5;
    const int g    = lane >> 2;
    const int tg   = lane & 3;
    const int wm   = warp >> 2;       // 0..3
    const int wn   = warp & 3;        // 0..3
    const int c0   = blockIdx.x * 128;
    const int m0   = blockIdx.y * 128;
    const int b    = blockIdx.z;
    const size_t bn0 = (size_t)b * N_;

    // per-thread cp.async slot: 1 chunk of A, 1 of B
    const int r0 = t >> 2, ch0 = t & 3;
    const __half* aP0 = g_V + (bn0 + m0 + r0) * C_ + ch0 * 8;
    const __half* bP0 = &g_M[b][c0 + r0][ch0 * 8];
    const uint32_t d0 = (uint32_t)(r0 * 80 + ch0 * 16);

    #define LOADSTAGE(st, k0) do {                                      \
        uint32_t sa = sbase + (uint32_t)(st) * ST_B;                     \
        CP16(sa + AREG_B + d0, aP0 + (k0));                              \
        CP16(sa + BREG_B + d0, bP0 + (k0));                              \
    } while (0)

    // ldmatrix per-thread byte offsets within a region
    const uint32_t a_off = (uint32_t)(
        (wm * 32 + ((lane >> 3) & 1) * 8 + (lane & 7)) * KPITCH
        + (lane >> 4) * 8) * 2;
    const uint32_t b_off = (uint32_t)(
        (wn * 32 + (lane >> 4) * 8 + (lane & 7)) * KPITCH
        + ((lane >> 3) & 1) * 8) * 2;

    float acc[2][4][4];
    #pragma unroll
    for (int a = 0; a < 2; a++)
        #pragma unroll
        for (int c = 0; c < 4; c++)
            #pragma unroll
            for (int q = 0; q < 4; q++) acc[a][c][q] = 0.f;

    LOADSTAGE(0, 0);  CPCOMMIT();
    LOADSTAGE(1, 32); CPCOMMIT();
    LOADSTAGE(2, 64); CPCOMMIT();

    for (int ks = 0; ks < 24; ks++) {
        CPWAIT2();
        __syncthreads();
        if (ks + 3 < 24) LOADSTAGE((ks + 3) & 3, (ks + 3) * 32);
        CPCOMMIT();

        const uint32_t sp = sbase + (uint32_t)(ks & 3) * ST_B;
        const uint32_t aB = sp + AREG_B + a_off;
        const uint32_t bB = sp + BREG_B + b_off;

        #pragma unroll
        for (int kk = 0; kk < 2; kk++) {
            const uint32_t kb = kk * 32;   // 16 fp16 = 32 bytes
            uint32_t ah[2][4], bh[2][4];
            #pragma unroll
            for (int mi = 0; mi < 2; mi++)
                LDSM4(ah[mi], aB + mi * 1280 + kb);
            #pragma unroll
            for (int np = 0; np < 2; np++)
                LDSM4(bh[np], bB + np * 1280 + kb);
            #pragma unroll
            for (int mi = 0; mi < 2; mi++) {
                #pragma unroll
                for (int ni = 0; ni < 4; ni++) {
                    const int np = ni >> 1, ix = (ni & 1) * 2;
                    mma16816(acc[mi][ni], ah[mi], bh[np][ix], bh[np][ix + 1]);
                }
            }
        }
    }

    // epilogue: bias add + store
    #pragma unroll
    for (int ni = 0; ni < 4; ni++) {
        const int col = wn * 32 + ni * 8 + 2 * tg;
        const float bv0 = bias[c0 + col];
        const float bv1 = bias[c0 + col + 1];
        #pragma unroll
        for (int mi = 0; mi < 2; mi++) {
            const int row = m0 + wm * 32 + mi * 16 + g;
            float* o = out + (bn0 + row) * C_ + c0 + col;
            float2 v0 = make_float2(acc[mi][ni][0] + bv0, acc[mi][ni][1] + bv1);
            float2 v1 = make_float2(acc[mi][ni][2] + bv0, acc[mi][ni][3] + bv1);
            *(float2*)o = v0;
            *(float2*)(o + 8 * C_) = v1;
        }
    }
}

// ============================================================
extern "C" void kernel_launch(void* const* d_in, const int* in_sizes, int n_in,
                              void* d_out, int out_size) {
    const float* x    = (const float*)d_in[0];
    const float* temp = (const float*)d_in[1];
    const float* w    = (const float*)d_in[2];
    const float* bias = (const float*)d_in[3];
    float* out = (float*)d_out;

    cudaFuncSetAttribute(gemm_kernel, cudaFuncAttributeMaxDynamicSharedMemorySize, GSMEM);

    qk_kernel<<<dim3(BH_, NSPLIT), 256>>>(x);
    xvcvt_kernel<<<(B_ * N_ * C_ / 8) / 256, 256>>>(x);
    mproj_kernel<<<BH_, 256>>>(w, temp);
    gemm_kernel<<<dim3(C_ / 128, N_ / 128, B_), 512, GSMEM>>>(bias, out);
}